// round 6
// baseline (speedup 1.0000x reference)
#include <cuda_runtime.h>
#include <cuda_bf16.h>
#include <cstdint>
#include <cstddef>

#define D128 128
#define NFEAT 10
#define N_IP 20000
#define N_CONN 100000
#define N_E 200000
#define T_ITERS 3

// ---------------- scratch (static device globals; no allocation) ----------------
__device__ float g_ip[N_IP * D128];
__device__ float g_conn[N_CONN * D128];
__device__ float g_XA[N_IP * D128];
__device__ float g_XB[N_CONN * D128];
__device__ float g_YA[N_CONN * D128];
__device__ float g_YB[N_IP * D128];
__device__ float g_agg_conn[N_CONN * D128];
__device__ float g_agg_ip[N_IP * D128];
__device__ float g_rc_conn[N_CONN];
__device__ float g_rc_ip[N_IP];
__device__ float g_H1[N_CONN * D128];
__device__ float g_H2[N_CONN * 64];

// bf16 hi/lo split, transposed weights [N][128]
__device__ __nv_bfloat16 g_m1t_h[128 * 128], g_m1t_l[128 * 128];
__device__ __nv_bfloat16 g_m1b_h[128 * 128], g_m1b_l[128 * 128];
__device__ __nv_bfloat16 g_m2t_h[128 * 128], g_m2t_l[128 * 128];
__device__ __nv_bfloat16 g_m2b_h[128 * 128], g_m2b_l[128 * 128];
__device__ __nv_bfloat16 g_gik_h[384 * 128], g_gik_l[384 * 128];
__device__ __nv_bfloat16 g_gir_h[384 * 128], g_gir_l[384 * 128];
__device__ __nv_bfloat16 g_gck_h[384 * 128], g_gck_l[384 * 128];
__device__ __nv_bfloat16 g_gcr_h[384 * 128], g_gcr_l[384 * 128];
__device__ __nv_bfloat16 g_wr1_h[128 * 128], g_wr1_l[128 * 128];
__device__ __nv_bfloat16 g_wr2_h[64 * 128],  g_wr2_l[64 * 128];

// ---------------- helpers ----------------
__device__ __forceinline__ uint32_t smem_u32(const void* p) {
    uint32_t a;
    asm("{ .reg .u64 t; cvta.to.shared.u64 t, %1; cvt.u32.u64 %0, t; }" : "=r"(a) : "l"(p));
    return a;
}
__device__ __forceinline__ void ldsm_x4(uint32_t& r0, uint32_t& r1, uint32_t& r2, uint32_t& r3,
                                        uint32_t addr) {
    asm volatile("ldmatrix.sync.aligned.m8n8.x4.shared.b16 {%0,%1,%2,%3}, [%4];"
                 : "=r"(r0), "=r"(r1), "=r"(r2), "=r"(r3) : "r"(addr));
}
__device__ __forceinline__ void mma16816(float* c, const uint32_t* a, const uint32_t* b) {
    asm volatile(
        "mma.sync.aligned.m16n8k16.row.col.f32.bf16.bf16.f32 "
        "{%0,%1,%2,%3}, {%4,%5,%6,%7}, {%8,%9}, {%0,%1,%2,%3};"
        : "+f"(c[0]), "+f"(c[1]), "+f"(c[2]), "+f"(c[3])
        : "r"(a[0]), "r"(a[1]), "r"(a[2]), "r"(a[3]), "r"(b[0]), "r"(b[1]));
}
__device__ __forceinline__ uint32_t pack_bf2(__nv_bfloat16 a, __nv_bfloat16 b) {
    return ((uint32_t)__bfloat16_as_ushort(b) << 16) | (uint32_t)__bfloat16_as_ushort(a);
}

// ---------------- HMMA GEMM: C[MxNtot] = act(rowscale(A[Mx128]) @ Wt^T + bias) ----------------
template <int NTILE>
__global__ __launch_bounds__(256) void mma_gemm(
    const float* __restrict__ A, const __nv_bfloat16* __restrict__ Bh,
    const __nv_bfloat16* __restrict__ Bl, float* __restrict__ C,
    int M, int ldc, const float* __restrict__ bias,
    const float* __restrict__ rscale, int do_relu)
{
    constexpr int WM = (NTILE == 128) ? 64 : 32;
    constexpr int MT = WM / 16;
    constexpr int A_HI = 0, A_LO = 32768, B_HI = 65536;
    constexpr int B_LO = B_HI + NTILE * 256;

    extern __shared__ char smem[];
    const uint32_t sb = smem_u32(smem);
    const int tid = threadIdx.x, wid = tid >> 5, lane = tid & 31;
    const int m0 = blockIdx.x * 128;
    const int col0 = blockIdx.y * NTILE;
    int wm, wn;
    if (NTILE == 128) { wm = wid & 1; wn = wid >> 1; }
    else              { wm = wid & 3; wn = wid >> 2; }

#pragma unroll
    for (int i = 0; i < 8; i++) {
        int idx = tid + i * 256;
        int r = idx >> 4, kc = idx & 15;
        int gr = m0 + r;
        float4 v0 = make_float4(0.f, 0.f, 0.f, 0.f), v1 = v0;
        if (gr < M) {
            const float* ap = A + (size_t)gr * 128 + kc * 8;
            v0 = *(const float4*)ap;
            v1 = *(const float4*)(ap + 4);
            if (rscale) {
                float s = rscale[gr];
                v0.x *= s; v0.y *= s; v0.z *= s; v0.w *= s;
                v1.x *= s; v1.y *= s; v1.z *= s; v1.w *= s;
            }
        }
        float f[8] = {v0.x, v0.y, v0.z, v0.w, v1.x, v1.y, v1.z, v1.w};
        uint32_t hw[4], lw[4];
#pragma unroll
        for (int j = 0; j < 4; j++) {
            __nv_bfloat16 h0 = __float2bfloat16(f[2 * j]);
            __nv_bfloat16 h1 = __float2bfloat16(f[2 * j + 1]);
            __nv_bfloat16 l0 = __float2bfloat16(f[2 * j] - __bfloat162float(h0));
            __nv_bfloat16 l1 = __float2bfloat16(f[2 * j + 1] - __bfloat162float(h1));
            hw[j] = pack_bf2(h0, h1);
            lw[j] = pack_bf2(l0, l1);
        }
        uint32_t sw = (uint32_t)(r * 256 + ((kc ^ (r & 7)) << 4));
        *(uint4*)(smem + A_HI + sw) = make_uint4(hw[0], hw[1], hw[2], hw[3]);
        *(uint4*)(smem + A_LO + sw) = make_uint4(lw[0], lw[1], lw[2], lw[3]);
    }
#pragma unroll
    for (int i = 0; i < NTILE / 16; i++) {
        int idx = tid + i * 256;
        int r = idx >> 4, kc = idx & 15;
        uint32_t sw = (uint32_t)(r * 256 + ((kc ^ (r & 7)) << 4));
        *(uint4*)(smem + B_HI + sw) = ((const uint4*)(Bh + (size_t)(col0 + r) * 128))[kc];
        *(uint4*)(smem + B_LO + sw) = ((const uint4*)(Bl + (size_t)(col0 + r) * 128))[kc];
    }
    __syncthreads();

    float acc[MT][4][4];
#pragma unroll
    for (int mt = 0; mt < MT; mt++)
#pragma unroll
        for (int nt = 0; nt < 4; nt++)
#pragma unroll
            for (int j = 0; j < 4; j++) acc[mt][nt][j] = 0.f;

    const int rA = ((lane >> 3) & 1) * 8 + (lane & 7);
    const int cA = lane >> 4;
    const int rB = ((lane >> 4) << 3) + (lane & 7);
    const int cB = (lane >> 3) & 1;

#pragma unroll
    for (int ks = 0; ks < 8; ks++) {
        const int kc0 = ks * 2;
        uint32_t ah[MT][4], al[MT][4], bh[4][2], bl[4][2];
#pragma unroll
        for (int mt = 0; mt < MT; mt++) {
            int row = wm * WM + mt * 16 + rA;
            uint32_t ad = sb + A_HI + row * 256 + (((kc0 + cA) ^ (row & 7)) << 4);
            ldsm_x4(ah[mt][0], ah[mt][1], ah[mt][2], ah[mt][3], ad);
            ldsm_x4(al[mt][0], al[mt][1], al[mt][2], al[mt][3], ad + (A_LO - A_HI));
        }
#pragma unroll
        for (int p = 0; p < 2; p++) {
            int row = wn * 32 + p * 16 + rB;
            uint32_t bd = sb + B_HI + row * 256 + (((kc0 + cB) ^ (row & 7)) << 4);
            uint32_t r0, r1, r2, r3;
            ldsm_x4(r0, r1, r2, r3, bd);
            bh[p * 2][0] = r0; bh[p * 2][1] = r1; bh[p * 2 + 1][0] = r2; bh[p * 2 + 1][1] = r3;
            ldsm_x4(r0, r1, r2, r3, bd + (B_LO - B_HI));
            bl[p * 2][0] = r0; bl[p * 2][1] = r1; bl[p * 2 + 1][0] = r2; bl[p * 2 + 1][1] = r3;
        }
#pragma unroll
        for (int mt = 0; mt < MT; mt++)
#pragma unroll
            for (int nt = 0; nt < 4; nt++) {
                mma16816(acc[mt][nt], ah[mt], bh[nt]);
                mma16816(acc[mt][nt], ah[mt], bl[nt]);
                mma16816(acc[mt][nt], al[mt], bh[nt]);
            }
    }

    const int rowg = lane >> 2, colg = (lane & 3) * 2;
#pragma unroll
    for (int mt = 0; mt < MT; mt++) {
#pragma unroll
        for (int nt = 0; nt < 4; nt++) {
            int gc = col0 + wn * 32 + nt * 8 + colg;
            float bx = 0.f, by = 0.f;
            if (bias) { bx = __ldg(bias + gc); by = __ldg(bias + gc + 1); }
#pragma unroll
            for (int h = 0; h < 2; h++) {
                int gr = m0 + wm * WM + mt * 16 + h * 8 + rowg;
                if (gr < M) {
                    float x = acc[mt][nt][h * 2 + 0] + bx;
                    float y = acc[mt][nt][h * 2 + 1] + by;
                    if (do_relu) { x = fmaxf(x, 0.f); y = fmaxf(y, 0.f); }
                    float2 o; o.x = x; o.y = y;
                    *(float2*)(C + (size_t)gr * ldc + gc) = o;
                }
            }
        }
    }
}

// ---------------- fused GRU: h' = GRU(rc*agg, h) with both 384-col GEMMs + gate in-block ----
// Block: 64 rows, 256 threads (warp grid 2m x 4n, warp tile 32 x 96).
// Phase 0: hm = h @ Wr  -> smem. Phase 1: xm = (rc*agg) @ Wk -> smem (aliases B region).
// Gate phase: fp32 math, reads exact h from gmem, writes h in place.
__global__ __launch_bounds__(256) void fused_gru(
    const float* __restrict__ agg, float* __restrict__ hstate,
    const __nv_bfloat16* __restrict__ Wk_h, const __nv_bfloat16* __restrict__ Wk_l,
    const __nv_bfloat16* __restrict__ Wr_h, const __nv_bfloat16* __restrict__ Wr_l,
    const float* __restrict__ gb,   // [2][384]
    const float* __restrict__ rscale, int M)
{
    constexpr int HM_STRIDE = 385;
    constexpr int HM_OFF = 0;                     // 64*385*4 = 98560
    constexpr int B_OFF  = 98560;                 // B half: hi 49152 + lo 49152
    constexpr int BL_OFF = B_OFF + 49152;
    constexpr int A_OFF  = B_OFF + 98304;         // A: hi 16384 + lo 16384
    constexpr int AL_OFF = A_OFF + 16384;
    constexpr int XM_OFF = B_OFF;                 // aliased after last MMA

    extern __shared__ char smem[];
    float* hm_s = (float*)(smem + HM_OFF);
    float* xm_s = (float*)(smem + XM_OFF);
    const uint32_t sb = smem_u32(smem);
    const int tid = threadIdx.x, wid = tid >> 5, lane = tid & 31;
    const int m0 = blockIdx.x * 64;
    const int wm = wid & 1, wn = wid >> 1;

    const int rA = ((lane >> 3) & 1) * 8 + (lane & 7);
    const int cA = lane >> 4;
    const int rB = ((lane >> 4) << 3) + (lane & 7);
    const int cB = (lane >> 3) & 1;

    float acc[2][12][4];

#pragma unroll 1
    for (int phase = 0; phase < 2; phase++) {
        const float* Asrc = phase ? agg : hstate;
        const bool use_rs = (phase == 1);
        const __nv_bfloat16* Wh = phase ? Wk_h : Wr_h;
        const __nv_bfloat16* Wl = phase ? Wk_l : Wr_l;

        // ---- load A tile (64 x 128 fp32 -> bf16 hi/lo, swizzled) ----
#pragma unroll
        for (int i = 0; i < 4; i++) {
            int idx = tid + i * 256;
            int r = idx >> 4, kc = idx & 15;
            int gr = m0 + r;
            float4 v0 = make_float4(0.f, 0.f, 0.f, 0.f), v1 = v0;
            if (gr < M) {
                const float* ap = Asrc + (size_t)gr * 128 + kc * 8;
                v0 = *(const float4*)ap;
                v1 = *(const float4*)(ap + 4);
                if (use_rs) {
                    float s = rscale[gr];
                    v0.x *= s; v0.y *= s; v0.z *= s; v0.w *= s;
                    v1.x *= s; v1.y *= s; v1.z *= s; v1.w *= s;
                }
            }
            float f[8] = {v0.x, v0.y, v0.z, v0.w, v1.x, v1.y, v1.z, v1.w};
            uint32_t hw[4], lw[4];
#pragma unroll
            for (int j = 0; j < 4; j++) {
                __nv_bfloat16 h0 = __float2bfloat16(f[2 * j]);
                __nv_bfloat16 h1 = __float2bfloat16(f[2 * j + 1]);
                __nv_bfloat16 l0 = __float2bfloat16(f[2 * j] - __bfloat162float(h0));
                __nv_bfloat16 l1 = __float2bfloat16(f[2 * j + 1] - __bfloat162float(h1));
                hw[j] = pack_bf2(h0, h1);
                lw[j] = pack_bf2(l0, l1);
            }
            uint32_t sw = (uint32_t)(r * 256 + ((kc ^ (r & 7)) << 4));
            *(uint4*)(smem + A_OFF + sw) = make_uint4(hw[0], hw[1], hw[2], hw[3]);
            *(uint4*)(smem + AL_OFF + sw) = make_uint4(lw[0], lw[1], lw[2], lw[3]);
        }

#pragma unroll
        for (int mt = 0; mt < 2; mt++)
#pragma unroll
            for (int nt = 0; nt < 12; nt++)
#pragma unroll
                for (int j = 0; j < 4; j++) acc[mt][nt][j] = 0.f;

#pragma unroll 1
        for (int half = 0; half < 2; half++) {
            __syncthreads();   // A stores visible; B region safe to overwrite
            // ---- load B K-half: 384 rows x 64 bf16 (8 x 16B chunks), hi/lo, swizzled ----
#pragma unroll
            for (int i = 0; i < 12; i++) {
                int idx = tid + i * 256;
                int r = idx >> 3, kc = idx & 7;
                uint32_t sw = (uint32_t)(r * 128 + ((kc ^ (r & 7)) << 4));
                *(uint4*)(smem + B_OFF + sw)  = ((const uint4*)(Wh + (size_t)r * 128 + half * 64))[kc];
                *(uint4*)(smem + BL_OFF + sw) = ((const uint4*)(Wl + (size_t)r * 128 + half * 64))[kc];
            }
            __syncthreads();

#pragma unroll
            for (int ks = 0; ks < 4; ks++) {
                uint32_t ah[2][4], al[2][4], bh[12][2], bl[12][2];
#pragma unroll
                for (int mt = 0; mt < 2; mt++) {
                    int row = wm * 32 + mt * 16 + rA;
                    uint32_t ad = sb + A_OFF + row * 256 +
                                  (((half * 8 + ks * 2 + cA) ^ (row & 7)) << 4);
                    ldsm_x4(ah[mt][0], ah[mt][1], ah[mt][2], ah[mt][3], ad);
                    ldsm_x4(al[mt][0], al[mt][1], al[mt][2], al[mt][3], ad + 16384);
                }
#pragma unroll
                for (int g = 0; g < 6; g++) {
                    int row = wn * 96 + g * 16 + rB;
                    uint32_t bd = sb + B_OFF + row * 128 +
                                  (((ks * 2 + cB) ^ (row & 7)) << 4);
                    uint32_t r0, r1, r2, r3;
                    ldsm_x4(r0, r1, r2, r3, bd);
                    bh[2 * g][0] = r0; bh[2 * g][1] = r1;
                    bh[2 * g + 1][0] = r2; bh[2 * g + 1][1] = r3;
                    ldsm_x4(r0, r1, r2, r3, bd + 49152);
                    bl[2 * g][0] = r0; bl[2 * g][1] = r1;
                    bl[2 * g + 1][0] = r2; bl[2 * g + 1][1] = r3;
                }
#pragma unroll
                for (int mt = 0; mt < 2; mt++)
#pragma unroll
                    for (int nt = 0; nt < 12; nt++) {
                        mma16816(acc[mt][nt], ah[mt], bh[nt]);
                        mma16816(acc[mt][nt], ah[mt], bl[nt]);
                        mma16816(acc[mt][nt], al[mt], bh[nt]);
                    }
            }
        }
        __syncthreads();   // all MMA done; A/B regions free

        // ---- store acc to hm_s (phase 0) or xm_s (phase 1, aliases B region) ----
        float* dst = phase ? xm_s : hm_s;
        const int rowg = lane >> 2, colg = (lane & 3) * 2;
#pragma unroll
        for (int mt = 0; mt < 2; mt++)
#pragma unroll
            for (int nt = 0; nt < 12; nt++)
#pragma unroll
                for (int hh = 0; hh < 2; hh++) {
                    int r = wm * 32 + mt * 16 + hh * 8 + rowg;
                    int c = wn * 96 + nt * 8 + colg;
                    dst[r * HM_STRIDE + c]     = acc[mt][nt][hh * 2 + 0];
                    dst[r * HM_STRIDE + c + 1] = acc[mt][nt][hh * 2 + 1];
                }
    }
    __syncthreads();

    // ---- gate phase: 64 rows x 128 cols; thread -> (row = tid/4, 32 cols) ----
    {
        int row = tid >> 2;
        int cb = (tid & 3) * 32;
        int grow = m0 + row;
        if (grow < M) {
            float* hp = hstate + (size_t)grow * 128;
#pragma unroll 4
            for (int i = 0; i < 32; i++) {
                int c = cb + i;
                float xz = xm_s[row * HM_STRIDE + c]       + __ldg(gb + c);
                float hz = hm_s[row * HM_STRIDE + c]       + __ldg(gb + 384 + c);
                float xr = xm_s[row * HM_STRIDE + 128 + c] + __ldg(gb + 128 + c);
                float hr = hm_s[row * HM_STRIDE + 128 + c] + __ldg(gb + 384 + 128 + c);
                float xh = xm_s[row * HM_STRIDE + 256 + c] + __ldg(gb + 256 + c);
                float hh = hm_s[row * HM_STRIDE + 256 + c] + __ldg(gb + 384 + 256 + c);
                float hv = hp[c];
                float z = 1.f / (1.f + expf(-(xz + hz)));
                float r = 1.f / (1.f + expf(-(xr + hr)));
                float cand = tanhf(xh + r * hh);
                hp[c] = z * hv + (1.f - z) * cand;
            }
        }
    }
}

// ---------------- weight prep: W[128 x N] -> transposed bf16 hi/lo [N x 128] ----------------
__global__ void prep_weight(const float* __restrict__ W, int N,
                            __nv_bfloat16* __restrict__ hi, __nv_bfloat16* __restrict__ lo)
{
    int idx = blockIdx.x * blockDim.x + threadIdx.x;
    if (idx >= N * 128) return;
    int n = idx >> 7, k = idx & 127;
    float x = W[(size_t)k * N + n];
    __nv_bfloat16 h = __float2bfloat16(x);
    hi[idx] = h;
    lo[idx] = __float2bfloat16(x - __bfloat162float(h));
}

// ---------------- small utility kernels ----------------
__global__ void fill_kernel(float* __restrict__ p, int n4, float v) {
    int i = blockIdx.x * blockDim.x + threadIdx.x;
    if (i < n4) *(float4*)(p + (size_t)i * 4) = make_float4(v, v, v, v);
}
__global__ void init_conn_kernel(float* __restrict__ p, const float* __restrict__ feat) {
    int i = blockIdx.x * blockDim.x + threadIdx.x;
    if (i < N_CONN * D128) {
        int r = i >> 7, c = i & 127;
        p[i] = (c < NFEAT) ? feat[r * NFEAT + c] : 0.f;
    }
}
__global__ void count_kernel(const int* __restrict__ dst, float* __restrict__ cnt, int e) {
    int i = blockIdx.x * blockDim.x + threadIdx.x;
    if (i < e) atomicAdd(cnt + dst[i], 1.f);
}
__global__ void recip_kernel(float* __restrict__ c, int n) {
    int i = blockIdx.x * blockDim.x + threadIdx.x;
    if (i < n) c[i] = 1.f / fmaxf(c[i], 1.f);
}

// ---------------- edge message + scatter-add ----------------
__global__ void edge_msg_kernel(
    const int* __restrict__ src, const int* __restrict__ dst,
    const float* __restrict__ XS, const float* __restrict__ XD,
    const float* __restrict__ bias, float* __restrict__ out_sum, int e)
{
    int gw = (blockIdx.x * blockDim.x + threadIdx.x) >> 5;
    if (gw >= e) return;
    int lane = threadIdx.x & 31;
    int s = __ldg(src + gw);
    int d = __ldg(dst + gw);
    int c = lane << 2;
    float4 a = *(const float4*)(XS + (size_t)s * 128 + c);
    float4 b = *(const float4*)(XD + (size_t)d * 128 + c);
    float4 bb = *(const float4*)(bias + c);
    float4 m;
    m.x = fmaxf(a.x + b.x + bb.x, 0.f);
    m.y = fmaxf(a.y + b.y + bb.y, 0.f);
    m.z = fmaxf(a.z + b.z + bb.z, 0.f);
    m.w = fmaxf(a.w + b.w + bb.w, 0.f);
    float* p = out_sum + (size_t)d * 128 + c;
    atomicAdd(p + 0, m.x);
    atomicAdd(p + 1, m.y);
    atomicAdd(p + 2, m.z);
    atomicAdd(p + 3, m.w);
}

// ---------------- readout tail ----------------
__global__ void readout_kernel(const float* __restrict__ H2, const float* __restrict__ W3,
                               const float* __restrict__ b3, float* __restrict__ out, int M)
{
    __shared__ float w[64 * 15];
    __shared__ float bb[15];
    for (int i = threadIdx.x; i < 64 * 15; i += blockDim.x) w[i] = W3[i];
    if (threadIdx.x < 15) bb[threadIdx.x] = b3[threadIdx.x];
    __syncthreads();
    int row = blockIdx.x * blockDim.x + threadIdx.x;
    if (row >= M) return;
    float acc[15];
#pragma unroll
    for (int j = 0; j < 15; j++) acc[j] = bb[j];
    const float* hrow = H2 + (size_t)row * 64;
#pragma unroll 16
    for (int k = 0; k < 64; k++) {
        float hv = __ldg(hrow + k);
#pragma unroll
        for (int j = 0; j < 15; j++) acc[j] += hv * w[k * 15 + j];
    }
    float mx = acc[0];
#pragma unroll
    for (int j = 1; j < 15; j++) mx = fmaxf(mx, acc[j]);
    float sum = 0.f;
#pragma unroll
    for (int j = 0; j < 15; j++) { acc[j] = expf(acc[j] - mx); sum += acc[j]; }
    float inv = 1.f / sum;
    float* op = out + (size_t)row * 15;
#pragma unroll
    for (int j = 0; j < 15; j++) op[j] = acc[j] * inv;
}

// ---------------- host side ----------------
static const int SMEM128 = 65536 + 128 * 512;          // 131072
static const int SMEM64  = 65536 + 64 * 512;           // 98304
static const int SMEM_GRU = 98560 + 98304 + 32768;     // 229632

static inline void launch_mma128(const float* A, const __nv_bfloat16* Bh,
                                 const __nv_bfloat16* Bl, float* C, int M, int Ntot,
                                 const float* bias, const float* rs, int relu) {
    dim3 g((M + 127) / 128, Ntot / 128);
    mma_gemm<128><<<g, 256, SMEM128>>>(A, Bh, Bl, C, M, Ntot, bias, rs, relu);
}
static inline void launch_mma64(const float* A, const __nv_bfloat16* Bh,
                                const __nv_bfloat16* Bl, float* C, int M,
                                const float* bias, int relu) {
    dim3 g((M + 127) / 128, 1);
    mma_gemm<64><<<g, 256, SMEM64>>>(A, Bh, Bl, C, M, 64, bias, nullptr, relu);
}
static inline void launch_zero(float* p, int n) {
    int n4 = n >> 2;
    fill_kernel<<<(n4 + 255) / 256, 256>>>(p, n4, 0.f);
}

extern "C" void kernel_launch(void* const* d_in, const int* in_sizes, int n_in,
                              void* d_out, int out_size)
{
    const float* feat  = (const float*)d_in[0];
    const int*   s_i2c = (const int*)d_in[1];
    const int*   d_i2c = (const int*)d_in[2];
    const int*   s_c2i = (const int*)d_in[3];
    const int*   d_c2i = (const int*)d_in[4];
    const float* W_m1  = (const float*)d_in[5];
    const float* b_m1  = (const float*)d_in[6];
    const float* W_m2  = (const float*)d_in[7];
    const float* b_m2  = (const float*)d_in[8];
    const float* gik   = (const float*)d_in[9];
    const float* gir   = (const float*)d_in[10];
    const float* gib   = (const float*)d_in[11];
    const float* gck   = (const float*)d_in[12];
    const float* gcr   = (const float*)d_in[13];
    const float* gcb   = (const float*)d_in[14];
    const float* Wr1   = (const float*)d_in[15];
    const float* br1   = (const float*)d_in[16];
    const float* Wr2   = (const float*)d_in[17];
    const float* br2   = (const float*)d_in[18];
    const float* Wr3   = (const float*)d_in[19];
    const float* br3   = (const float*)d_in[20];
    float* out = (float*)d_out;

    cudaFuncSetAttribute(mma_gemm<128>, cudaFuncAttributeMaxDynamicSharedMemorySize, SMEM128);
    cudaFuncSetAttribute(mma_gemm<64>,  cudaFuncAttributeMaxDynamicSharedMemorySize, SMEM64);
    cudaFuncSetAttribute(fused_gru,     cudaFuncAttributeMaxDynamicSharedMemorySize, SMEM_GRU);

    void* p;
    cudaGetSymbolAddress(&p, g_ip);       float* ip       = (float*)p;
    cudaGetSymbolAddress(&p, g_conn);     float* conn     = (float*)p;
    cudaGetSymbolAddress(&p, g_XA);       float* XA       = (float*)p;
    cudaGetSymbolAddress(&p, g_XB);       float* XB       = (float*)p;
    cudaGetSymbolAddress(&p, g_YA);       float* YA       = (float*)p;
    cudaGetSymbolAddress(&p, g_YB);       float* YB       = (float*)p;
    cudaGetSymbolAddress(&p, g_agg_conn); float* agg_conn = (float*)p;
    cudaGetSymbolAddress(&p, g_agg_ip);   float* agg_ip   = (float*)p;
    cudaGetSymbolAddress(&p, g_rc_conn);  float* rc_conn  = (float*)p;
    cudaGetSymbolAddress(&p, g_rc_ip);    float* rc_ip    = (float*)p;
    cudaGetSymbolAddress(&p, g_H1);       float* H1       = (float*)p;
    cudaGetSymbolAddress(&p, g_H2);       float* H2       = (float*)p;

    __nv_bfloat16 *m1t_h, *m1t_l, *m1b_h, *m1b_l, *m2t_h, *m2t_l, *m2b_h, *m2b_l;
    __nv_bfloat16 *gik_h, *gik_l, *gir_h, *gir_l, *gck_h, *gck_l, *gcr_h, *gcr_l;
    __nv_bfloat16 *wr1_h, *wr1_l, *wr2_h, *wr2_l;
    cudaGetSymbolAddress(&p, g_m1t_h); m1t_h = (__nv_bfloat16*)p;
    cudaGetSymbolAddress(&p, g_m1t_l); m1t_l = (__nv_bfloat16*)p;
    cudaGetSymbolAddress(&p, g_m1b_h); m1b_h = (__nv_bfloat16*)p;
    cudaGetSymbolAddress(&p, g_m1b_l); m1b_l = (__nv_bfloat16*)p;
    cudaGetSymbolAddress(&p, g_m2t_h); m2t_h = (__nv_bfloat16*)p;
    cudaGetSymbolAddress(&p, g_m2t_l); m2t_l = (__nv_bfloat16*)p;
    cudaGetSymbolAddress(&p, g_m2b_h); m2b_h = (__nv_bfloat16*)p;
    cudaGetSymbolAddress(&p, g_m2b_l); m2b_l = (__nv_bfloat16*)p;
    cudaGetSymbolAddress(&p, g_gik_h); gik_h = (__nv_bfloat16*)p;
    cudaGetSymbolAddress(&p, g_gik_l); gik_l = (__nv_bfloat16*)p;
    cudaGetSymbolAddress(&p, g_gir_h); gir_h = (__nv_bfloat16*)p;
    cudaGetSymbolAddress(&p, g_gir_l); gir_l = (__nv_bfloat16*)p;
    cudaGetSymbolAddress(&p, g_gck_h); gck_h = (__nv_bfloat16*)p;
    cudaGetSymbolAddress(&p, g_gck_l); gck_l = (__nv_bfloat16*)p;
    cudaGetSymbolAddress(&p, g_gcr_h); gcr_h = (__nv_bfloat16*)p;
    cudaGetSymbolAddress(&p, g_gcr_l); gcr_l = (__nv_bfloat16*)p;
    cudaGetSymbolAddress(&p, g_wr1_h); wr1_h = (__nv_bfloat16*)p;
    cudaGetSymbolAddress(&p, g_wr1_l); wr1_l = (__nv_bfloat16*)p;
    cudaGetSymbolAddress(&p, g_wr2_h); wr2_h = (__nv_bfloat16*)p;
    cudaGetSymbolAddress(&p, g_wr2_l); wr2_l = (__nv_bfloat16*)p;

    // --- weight prep (transpose + bf16 hi/lo split) ---
    prep_weight<<<(128 * 128 + 255) / 256, 256>>>(W_m1, 128, m1t_h, m1t_l);
    prep_weight<<<(128 * 128 + 255) / 256, 256>>>(W_m1 + 128 * 128, 128, m1b_h, m1b_l);
    prep_weight<<<(128 * 128 + 255) / 256, 256>>>(W_m2, 128, m2t_h, m2t_l);
    prep_weight<<<(128 * 128 + 255) / 256, 256>>>(W_m2 + 128 * 128, 128, m2b_h, m2b_l);
    prep_weight<<<(384 * 128 + 255) / 256, 256>>>(gik, 384, gik_h, gik_l);
    prep_weight<<<(384 * 128 + 255) / 256, 256>>>(gir, 384, gir_h, gir_l);
    prep_weight<<<(384 * 128 + 255) / 256, 256>>>(gck, 384, gck_h, gck_l);
    prep_weight<<<(384 * 128 + 255) / 256, 256>>>(gcr, 384, gcr_h, gcr_l);
    prep_weight<<<(128 * 128 + 255) / 256, 256>>>(Wr1, 128, wr1_h, wr1_l);
    prep_weight<<<(64 * 128 + 255) / 256, 256>>>(Wr2, 64, wr2_h, wr2_l);

    // --- segment counts (reciprocals) ---
    launch_zero(rc_conn, N_CONN);
    launch_zero(rc_ip, N_IP);
    count_kernel<<<(N_E + 255) / 256, 256>>>(d_i2c, rc_conn, N_E);
    count_kernel<<<(N_E + 255) / 256, 256>>>(d_c2i, rc_ip, N_E);
    recip_kernel<<<(N_CONN + 255) / 256, 256>>>(rc_conn, N_CONN);
    recip_kernel<<<(N_IP + 255) / 256, 256>>>(rc_ip, N_IP);

    // --- init states ---
    fill_kernel<<<((N_IP * D128 / 4) + 255) / 256, 256>>>(ip, N_IP * D128 / 4, 1.f);
    init_conn_kernel<<<(N_CONN * D128 + 255) / 256, 256>>>(conn, feat);

    const int edge_blocks = (N_E * 32 + 255) / 256;

    for (int t = 0; t < T_ITERS; t++) {
        // per-node halves of the message MLPs (factorized concat-GEMM)
        launch_mma128(ip,   m1t_h, m1t_l, XA, N_IP,   128, nullptr, nullptr, 0);
        launch_mma128(conn, m1b_h, m1b_l, XB, N_CONN, 128, nullptr, nullptr, 0);
        launch_mma128(conn, m2t_h, m2t_l, YA, N_CONN, 128, nullptr, nullptr, 0);
        launch_mma128(ip,   m2b_h, m2b_l, YB, N_IP,   128, nullptr, nullptr, 0);

        launch_zero(agg_conn, N_CONN * D128);
        launch_zero(agg_ip, N_IP * D128);

        edge_msg_kernel<<<edge_blocks, 256>>>(s_i2c, d_i2c, XA, XB, b_m1, agg_conn, N_E);
        edge_msg_kernel<<<edge_blocks, 256>>>(s_c2i, d_c2i, YA, YB, b_m2, agg_ip, N_E);

        // fused GRU update (both GEMMs + gate, state updated in place)
        fused_gru<<<(N_IP + 63) / 64, 256, SMEM_GRU>>>(
            agg_ip, ip, gik_h, gik_l, gir_h, gir_l, gib, rc_ip, N_IP);
        fused_gru<<<(N_CONN + 63) / 64, 256, SMEM_GRU>>>(
            agg_conn, conn, gck_h, gck_l, gcr_h, gcr_l, gcb, rc_conn, N_CONN);
    }

    // --- readout ---
    launch_mma128(conn, wr1_h, wr1_l, H1, N_CONN, 128, br1, nullptr, 1);
    launch_mma64(H1, wr2_h, wr2_l, H2, N_CONN, br2, 1);
    readout_kernel<<<(N_CONN + 127) / 128, 128>>>(H2, Wr3, br3, out, N_CONN);
}

// round 9
// speedup vs baseline: 1.1219x; 1.1219x over previous
#include <cuda_runtime.h>
#include <cuda_bf16.h>
#include <cstdint>
#include <cstddef>

#define D128 128
#define NFEAT 10
#define N_IP 20000
#define N_CONN 100000
#define N_E 200000
#define T_ITERS 3

// ---------------- scratch (static device globals; no allocation) ----------------
__device__ float g_ip[N_IP * D128];
__device__ float g_conn[N_CONN * D128];
__device__ float g_msg_ip[N_IP * 256];      // [XA | YB]
__device__ float g_msg_conn[N_CONN * 256];  // [XB | YA]
__device__ float g_agg_conn[N_CONN * D128];
__device__ float g_agg_ip[N_IP * D128];
__device__ float g_zr_ip[N_IP * 256];
__device__ float g_zr_c[N_CONN * 256];
__device__ float g_xh_ip[N_IP * D128];
__device__ float g_hh_ip[N_IP * D128];
__device__ float g_xh_c[N_CONN * D128];
__device__ float g_hh_c[N_CONN * D128];
__device__ float g_rc_conn[N_CONN];
__device__ float g_rc_ip[N_IP];
__device__ float g_H1[N_CONN * D128];
__device__ float g_H2[N_CONN * 64];

// bf16 hi/lo split, transposed weights [N][128]
__device__ __nv_bfloat16 g_ipcat_h[256 * 128], g_ipcat_l[256 * 128];    // [XA w | YB w]
__device__ __nv_bfloat16 g_conncat_h[256 * 128], g_conncat_l[256 * 128];// [XB w | YA w]
__device__ __nv_bfloat16 g_gik_h[384 * 128], g_gik_l[384 * 128];
__device__ __nv_bfloat16 g_gir_h[384 * 128], g_gir_l[384 * 128];
__device__ __nv_bfloat16 g_gck_h[384 * 128], g_gck_l[384 * 128];
__device__ __nv_bfloat16 g_gcr_h[384 * 128], g_gcr_l[384 * 128];
__device__ __nv_bfloat16 g_wr1_h[128 * 128], g_wr1_l[128 * 128];
__device__ __nv_bfloat16 g_wr2_h[64 * 128],  g_wr2_l[64 * 128];

// ---------------- helpers ----------------
__device__ __forceinline__ uint32_t smem_u32(const void* p) {
    uint32_t a;
    asm("{ .reg .u64 t; cvta.to.shared.u64 t, %1; cvt.u32.u64 %0, t; }" : "=r"(a) : "l"(p));
    return a;
}
__device__ __forceinline__ void ldsm_x4(uint32_t& r0, uint32_t& r1, uint32_t& r2, uint32_t& r3,
                                        uint32_t addr) {
    asm volatile("ldmatrix.sync.aligned.m8n8.x4.shared.b16 {%0,%1,%2,%3}, [%4];"
                 : "=r"(r0), "=r"(r1), "=r"(r2), "=r"(r3) : "r"(addr));
}
__device__ __forceinline__ void mma16816(float* c, const uint32_t* a, const uint32_t* b) {
    asm volatile(
        "mma.sync.aligned.m16n8k16.row.col.f32.bf16.bf16.f32 "
        "{%0,%1,%2,%3}, {%4,%5,%6,%7}, {%8,%9}, {%0,%1,%2,%3};"
        : "+f"(c[0]), "+f"(c[1]), "+f"(c[2]), "+f"(c[3])
        : "r"(a[0]), "r"(a[1]), "r"(a[2]), "r"(a[3]), "r"(b[0]), "r"(b[1]));
}
__device__ __forceinline__ uint32_t pack_bf2(__nv_bfloat16 a, __nv_bfloat16 b) {
    return ((uint32_t)__bfloat16_as_ushort(b) << 16) | (uint32_t)__bfloat16_as_ushort(a);
}

// ---------------- HMMA GEMM: C[MxNtot] = act(rowscale(A[Mx128]) @ Wt^T + bias) ----------------
// Optional second pass (A2,Bh2,Bl2): acc += A2 @ B2^T (no rowscale) -> K=256 accumulation.
template <int NTILE>
__global__ __launch_bounds__(256) void mma_gemm(
    const float* __restrict__ A, const __nv_bfloat16* __restrict__ Bh,
    const __nv_bfloat16* __restrict__ Bl, float* __restrict__ C,
    int M, int ldc, const float* __restrict__ bias,
    const float* __restrict__ rscale, int do_relu,
    const float* __restrict__ A2, const __nv_bfloat16* __restrict__ Bh2,
    const __nv_bfloat16* __restrict__ Bl2)
{
    constexpr int WM = (NTILE == 128) ? 64 : 32;
    constexpr int MT = WM / 16;
    constexpr int A_HI = 0, A_LO = 32768, B_HI = 65536;
    constexpr int B_LO = B_HI + NTILE * 256;

    extern __shared__ char smem[];
    const uint32_t sb = smem_u32(smem);
    const int tid = threadIdx.x, wid = tid >> 5, lane = tid & 31;
    const int m0 = blockIdx.x * 128;
    const int col0 = blockIdx.y * NTILE;
    int wm, wn;
    if (NTILE == 128) { wm = wid & 1; wn = wid >> 1; }
    else              { wm = wid & 3; wn = wid >> 2; }

    float acc[MT][4][4];
#pragma unroll
    for (int mt = 0; mt < MT; mt++)
#pragma unroll
        for (int nt = 0; nt < 4; nt++)
#pragma unroll
            for (int j = 0; j < 4; j++) acc[mt][nt][j] = 0.f;

    const int rA = ((lane >> 3) & 1) * 8 + (lane & 7);
    const int cA = lane >> 4;
    const int rB = ((lane >> 4) << 3) + (lane & 7);
    const int cB = (lane >> 3) & 1;

    const int npass = A2 ? 2 : 1;
#pragma unroll 1
    for (int pass = 0; pass < npass; pass++) {
        const float* Asrc = pass ? A2 : A;
        const __nv_bfloat16* Bhs = pass ? Bh2 : Bh;
        const __nv_bfloat16* Bls = pass ? Bl2 : Bl;
        const float* rs = pass ? nullptr : rscale;

        if (pass) __syncthreads();   // protect smem from prior mainloop readers

#pragma unroll
        for (int i = 0; i < 8; i++) {
            int idx = tid + i * 256;
            int r = idx >> 4, kc = idx & 15;
            int gr = m0 + r;
            float4 v0 = make_float4(0.f, 0.f, 0.f, 0.f), v1 = v0;
            if (gr < M) {
                const float* ap = Asrc + (size_t)gr * 128 + kc * 8;
                v0 = *(const float4*)ap;
                v1 = *(const float4*)(ap + 4);
                if (rs) {
                    float s = rs[gr];
                    v0.x *= s; v0.y *= s; v0.z *= s; v0.w *= s;
                    v1.x *= s; v1.y *= s; v1.z *= s; v1.w *= s;
                }
            }
            float f[8] = {v0.x, v0.y, v0.z, v0.w, v1.x, v1.y, v1.z, v1.w};
            uint32_t hw[4], lw[4];
#pragma unroll
            for (int j = 0; j < 4; j++) {
                __nv_bfloat16 h0 = __float2bfloat16(f[2 * j]);
                __nv_bfloat16 h1 = __float2bfloat16(f[2 * j + 1]);
                __nv_bfloat16 l0 = __float2bfloat16(f[2 * j] - __bfloat162float(h0));
                __nv_bfloat16 l1 = __float2bfloat16(f[2 * j + 1] - __bfloat162float(h1));
                hw[j] = pack_bf2(h0, h1);
                lw[j] = pack_bf2(l0, l1);
            }
            uint32_t sw = (uint32_t)(r * 256 + ((kc ^ (r & 7)) << 4));
            *(uint4*)(smem + A_HI + sw) = make_uint4(hw[0], hw[1], hw[2], hw[3]);
            *(uint4*)(smem + A_LO + sw) = make_uint4(lw[0], lw[1], lw[2], lw[3]);
        }
#pragma unroll
        for (int i = 0; i < NTILE / 16; i++) {
            int idx = tid + i * 256;
            int r = idx >> 4, kc = idx & 15;
            uint32_t sw = (uint32_t)(r * 256 + ((kc ^ (r & 7)) << 4));
            *(uint4*)(smem + B_HI + sw) = ((const uint4*)(Bhs + (size_t)(col0 + r) * 128))[kc];
            *(uint4*)(smem + B_LO + sw) = ((const uint4*)(Bls + (size_t)(col0 + r) * 128))[kc];
        }
        __syncthreads();

#pragma unroll
        for (int ks = 0; ks < 8; ks++) {
            const int kc0 = ks * 2;
            uint32_t ah[MT][4], al[MT][4], bh[4][2], bl[4][2];
#pragma unroll
            for (int mt = 0; mt < MT; mt++) {
                int row = wm * WM + mt * 16 + rA;
                uint32_t ad = sb + A_HI + row * 256 + (((kc0 + cA) ^ (row & 7)) << 4);
                ldsm_x4(ah[mt][0], ah[mt][1], ah[mt][2], ah[mt][3], ad);
                ldsm_x4(al[mt][0], al[mt][1], al[mt][2], al[mt][3], ad + (A_LO - A_HI));
            }
#pragma unroll
            for (int p = 0; p < 2; p++) {
                int row = wn * 32 + p * 16 + rB;
                uint32_t bd = sb + B_HI + row * 256 + (((kc0 + cB) ^ (row & 7)) << 4);
                uint32_t r0, r1, r2, r3;
                ldsm_x4(r0, r1, r2, r3, bd);
                bh[p * 2][0] = r0; bh[p * 2][1] = r1; bh[p * 2 + 1][0] = r2; bh[p * 2 + 1][1] = r3;
                ldsm_x4(r0, r1, r2, r3, bd + (B_LO - B_HI));
                bl[p * 2][0] = r0; bl[p * 2][1] = r1; bl[p * 2 + 1][0] = r2; bl[p * 2 + 1][1] = r3;
            }
#pragma unroll
            for (int mt = 0; mt < MT; mt++)
#pragma unroll
                for (int nt = 0; nt < 4; nt++) {
                    mma16816(acc[mt][nt], ah[mt], bh[nt]);
                    mma16816(acc[mt][nt], ah[mt], bl[nt]);
                    mma16816(acc[mt][nt], al[mt], bh[nt]);
                }
        }
    }

    const int rowg = lane >> 2, colg = (lane & 3) * 2;
#pragma unroll
    for (int mt = 0; mt < MT; mt++) {
#pragma unroll
        for (int nt = 0; nt < 4; nt++) {
            int gc = col0 + wn * 32 + nt * 8 + colg;
            float bx = 0.f, by = 0.f;
            if (bias) { bx = __ldg(bias + gc); by = __ldg(bias + gc + 1); }
#pragma unroll
            for (int h = 0; h < 2; h++) {
                int gr = m0 + wm * WM + mt * 16 + h * 8 + rowg;
                if (gr < M) {
                    float x = acc[mt][nt][h * 2 + 0] + bx;
                    float y = acc[mt][nt][h * 2 + 1] + by;
                    if (do_relu) { x = fmaxf(x, 0.f); y = fmaxf(y, 0.f); }
                    float2 o; o.x = x; o.y = y;
                    *(float2*)(C + (size_t)gr * ldc + gc) = o;
                }
            }
        }
    }
}

// ---------------- merged weight prep: 10 transposes + bf16 hi/lo split, one launch ----------
// Device-side job table over __device__ symbols (no struct parameter).
__global__ void prep_all(const float* __restrict__ W_m1, const float* __restrict__ W_m2,
                         const float* __restrict__ gik, const float* __restrict__ gir,
                         const float* __restrict__ gck, const float* __restrict__ gcr,
                         const float* __restrict__ Wr1, const float* __restrict__ Wr2)
{
    int idx = blockIdx.x * blockDim.x + threadIdx.x;
    const float* src;
    __nv_bfloat16 *hi, *lo;
    int ldN, l;
    if (idx < 65536) {                       // 4 jobs x 16384 (128x128 each)
        int j = idx >> 14;
        l = idx & 16383;
        ldN = 128;
        if (j == 0)      { src = W_m1;          hi = g_ipcat_h;           lo = g_ipcat_l; }
        else if (j == 1) { src = W_m2 + 16384;  hi = g_ipcat_h + 16384;   lo = g_ipcat_l + 16384; }
        else if (j == 2) { src = W_m1 + 16384;  hi = g_conncat_h;         lo = g_conncat_l; }
        else             { src = W_m2;          hi = g_conncat_h + 16384; lo = g_conncat_l + 16384; }
    } else if (idx < 262144) {               // 4 jobs x 49152 (384x128 each)
        int t = idx - 65536;
        int j = t / 49152;
        l = t % 49152;
        ldN = 384;
        if (j == 0)      { src = gik; hi = g_gik_h; lo = g_gik_l; }
        else if (j == 1) { src = gir; hi = g_gir_h; lo = g_gir_l; }
        else if (j == 2) { src = gck; hi = g_gck_h; lo = g_gck_l; }
        else             { src = gcr; hi = g_gcr_h; lo = g_gcr_l; }
    } else if (idx < 278528) {               // Wr1: 16384
        l = idx - 262144;
        ldN = 128;
        src = Wr1; hi = g_wr1_h; lo = g_wr1_l;
    } else if (idx < 286720) {               // Wr2: 8192
        l = idx - 278528;
        ldN = 64;
        src = Wr2; hi = g_wr2_h; lo = g_wr2_l;
    } else {
        return;
    }
    int n = l >> 7, k = l & 127;
    float x = src[(size_t)k * ldN + n];
    __nv_bfloat16 h = __float2bfloat16(x);
    hi[l] = h;
    lo[l] = __float2bfloat16(x - __bfloat162float(h));
}

// ---------------- small utility kernels ----------------
__global__ void init_states(float* __restrict__ ip, float* __restrict__ conn,
                            const float* __restrict__ feat) {
    int i = blockIdx.x * blockDim.x + threadIdx.x;
    if (i < N_CONN * D128) {
        int r = i >> 7, c = i & 127;
        conn[i] = (c < NFEAT) ? feat[r * NFEAT + c] : 0.f;
        if (i < N_IP * D128) ip[i] = 1.f;
    }
}
__global__ void zero_rc(float* __restrict__ c1, float* __restrict__ c2) {
    int i = blockIdx.x * blockDim.x + threadIdx.x;
    if (i < N_CONN) c1[i] = 0.f;
    if (i < N_IP) c2[i] = 0.f;
}
__global__ void count2(const int* __restrict__ d1, const int* __restrict__ d2,
                       float* __restrict__ c1, float* __restrict__ c2) {
    int i = blockIdx.x * blockDim.x + threadIdx.x;
    if (i < N_E) atomicAdd(c1 + d1[i], 1.f);
    else if (i < 2 * N_E) atomicAdd(c2 + d2[i - N_E], 1.f);
}
__global__ void recip2(float* __restrict__ c1, float* __restrict__ c2) {
    int i = blockIdx.x * blockDim.x + threadIdx.x;
    if (i < N_CONN) c1[i] = 1.f / fmaxf(c1[i], 1.f);
    if (i < N_IP) c2[i] = 1.f / fmaxf(c2[i], 1.f);
}
__global__ void zero2(float* __restrict__ a, int n4a, float* __restrict__ b, int n4b) {
    int i = blockIdx.x * blockDim.x + threadIdx.x;
    if (i < n4a) *(float4*)(a + (size_t)i * 4) = make_float4(0.f, 0.f, 0.f, 0.f);
    else if (i < n4a + n4b)
        *(float4*)(b + (size_t)(i - n4a) * 4) = make_float4(0.f, 0.f, 0.f, 0.f);
}

// ---------------- edge message + scatter-add (strided sources) ----------------
__global__ void edge_msg_kernel(
    const int* __restrict__ src, const int* __restrict__ dst,
    const float* __restrict__ XS, const float* __restrict__ XD, int ld,
    const float* __restrict__ bias, float* __restrict__ out_sum, int e)
{
    int gw = (blockIdx.x * blockDim.x + threadIdx.x) >> 5;
    if (gw >= e) return;
    int lane = threadIdx.x & 31;
    int s = __ldg(src + gw);
    int d = __ldg(dst + gw);
    int c = lane << 2;
    float4 a = *(const float4*)(XS + (size_t)s * ld + c);
    float4 b = *(const float4*)(XD + (size_t)d * ld + c);
    float4 bb = *(const float4*)(bias + c);
    float4 m;
    m.x = fmaxf(a.x + b.x + bb.x, 0.f);
    m.y = fmaxf(a.y + b.y + bb.y, 0.f);
    m.z = fmaxf(a.z + b.z + bb.z, 0.f);
    m.w = fmaxf(a.w + b.w + bb.w, 0.f);
    float* p = out_sum + (size_t)d * 128 + c;
    atomicAdd(p + 0, m.x);
    atomicAdd(p + 1, m.y);
    atomicAdd(p + 2, m.z);
    atomicAdd(p + 3, m.w);
}

// ---------------- GRU gate: z,r from zr_pre (K=256 merged GEMM); cand from xh + r*hh ------
__global__ void gru_gate2(float* __restrict__ h, const float* __restrict__ zrp,
                          const float* __restrict__ xh, const float* __restrict__ hhm,
                          const float* __restrict__ gb, int M)
{
    int idx = blockIdx.x * blockDim.x + threadIdx.x;
    if (idx >= M * 32) return;
    int row = idx >> 5;
    int c = (idx & 31) << 2;
    float4 z4 = *(const float4*)(zrp + (size_t)row * 256 + c);
    float4 r4 = *(const float4*)(zrp + (size_t)row * 256 + 128 + c);
    float4 x4 = *(const float4*)(xh + (size_t)row * 128 + c);
    float4 m4 = *(const float4*)(hhm + (size_t)row * 128 + c);
    float4 b0z = *(const float4*)(gb + c);
    float4 b1z = *(const float4*)(gb + 384 + c);
    float4 b0r = *(const float4*)(gb + 128 + c);
    float4 b1r = *(const float4*)(gb + 512 + c);
    float4 b0h = *(const float4*)(gb + 256 + c);
    float4 b1h = *(const float4*)(gb + 640 + c);
    float* hp = h + (size_t)row * 128 + c;
    float4 hv = *(const float4*)hp;
    float4 o;
    {
        float z = 1.f / (1.f + expf(-(z4.x + b0z.x + b1z.x)));
        float r = 1.f / (1.f + expf(-(r4.x + b0r.x + b1r.x)));
        float cd = tanhf(x4.x + b0h.x + r * (m4.x + b1h.x));
        o.x = z * hv.x + (1.f - z) * cd;
    }
    {
        float z = 1.f / (1.f + expf(-(z4.y + b0z.y + b1z.y)));
        float r = 1.f / (1.f + expf(-(r4.y + b0r.y + b1r.y)));
        float cd = tanhf(x4.y + b0h.y + r * (m4.y + b1h.y));
        o.y = z * hv.y + (1.f - z) * cd;
    }
    {
        float z = 1.f / (1.f + expf(-(z4.z + b0z.z + b1z.z)));
        float r = 1.f / (1.f + expf(-(r4.z + b0r.z + b1r.z)));
        float cd = tanhf(x4.z + b0h.z + r * (m4.z + b1h.z));
        o.z = z * hv.z + (1.f - z) * cd;
    }
    {
        float z = 1.f / (1.f + expf(-(z4.w + b0z.w + b1z.w)));
        float r = 1.f / (1.f + expf(-(r4.w + b0r.w + b1r.w)));
        float cd = tanhf(x4.w + b0h.w + r * (m4.w + b1h.w));
        o.w = z * hv.w + (1.f - z) * cd;
    }
    *(float4*)hp = o;
}

// ---------------- readout tail ----------------
__global__ void readout_kernel(const float* __restrict__ H2, const float* __restrict__ W3,
                               const float* __restrict__ b3, float* __restrict__ out, int M)
{
    __shared__ float w[64 * 15];
    __shared__ float bb[15];
    for (int i = threadIdx.x; i < 64 * 15; i += blockDim.x) w[i] = W3[i];
    if (threadIdx.x < 15) bb[threadIdx.x] = b3[threadIdx.x];
    __syncthreads();
    int row = blockIdx.x * blockDim.x + threadIdx.x;
    if (row >= M) return;
    float acc[15];
#pragma unroll
    for (int j = 0; j < 15; j++) acc[j] = bb[j];
    const float* hrow = H2 + (size_t)row * 64;
#pragma unroll 16
    for (int k = 0; k < 64; k++) {
        float hv = __ldg(hrow + k);
#pragma unroll
        for (int j = 0; j < 15; j++) acc[j] += hv * w[k * 15 + j];
    }
    float mx = acc[0];
#pragma unroll
    for (int j = 1; j < 15; j++) mx = fmaxf(mx, acc[j]);
    float sum = 0.f;
#pragma unroll
    for (int j = 0; j < 15; j++) { acc[j] = expf(acc[j] - mx); sum += acc[j]; }
    float inv = 1.f / sum;
    float* op = out + (size_t)row * 15;
#pragma unroll
    for (int j = 0; j < 15; j++) op[j] = acc[j] * inv;
}

// ---------------- host side ----------------
static const int SMEM128 = 65536 + 128 * 512;  // 131072
static const int SMEM64  = 65536 + 64 * 512;   // 98304

static inline void launch_g128(const float* A, const __nv_bfloat16* Bh, const __nv_bfloat16* Bl,
                               float* C, int M, int Ntot, int ldc, const float* bias,
                               const float* rs, int relu,
                               const float* A2 = nullptr, const __nv_bfloat16* Bh2 = nullptr,
                               const __nv_bfloat16* Bl2 = nullptr) {
    dim3 g((M + 127) / 128, Ntot / 128);
    mma_gemm<128><<<g, 256, SMEM128>>>(A, Bh, Bl, C, M, ldc, bias, rs, relu, A2, Bh2, Bl2);
}

extern "C" void kernel_launch(void* const* d_in, const int* in_sizes, int n_in,
                              void* d_out, int out_size)
{
    const float* feat  = (const float*)d_in[0];
    const int*   s_i2c = (const int*)d_in[1];
    const int*   d_i2c = (const int*)d_in[2];
    const int*   s_c2i = (const int*)d_in[3];
    const int*   d_c2i = (const int*)d_in[4];
    const float* W_m1  = (const float*)d_in[5];
    const float* b_m1  = (const float*)d_in[6];
    const float* W_m2  = (const float*)d_in[7];
    const float* b_m2  = (const float*)d_in[8];
    const float* gik   = (const float*)d_in[9];
    const float* gir   = (const float*)d_in[10];
    const float* gib   = (const float*)d_in[11];
    const float* gck   = (const float*)d_in[12];
    const float* gcr   = (const float*)d_in[13];
    const float* gcb   = (const float*)d_in[14];
    const float* Wr1   = (const float*)d_in[15];
    const float* br1   = (const float*)d_in[16];
    const float* Wr2   = (const float*)d_in[17];
    const float* br2   = (const float*)d_in[18];
    const float* Wr3   = (const float*)d_in[19];
    const float* br3   = (const float*)d_in[20];
    float* out = (float*)d_out;

    cudaFuncSetAttribute(mma_gemm<128>, cudaFuncAttributeMaxDynamicSharedMemorySize, SMEM128);
    cudaFuncSetAttribute(mma_gemm<64>,  cudaFuncAttributeMaxDynamicSharedMemorySize, SMEM64);

    void* p;
    cudaGetSymbolAddress(&p, g_ip);       float* ip       = (float*)p;
    cudaGetSymbolAddress(&p, g_conn);     float* conn     = (float*)p;
    cudaGetSymbolAddress(&p, g_msg_ip);   float* msg_ip   = (float*)p;
    cudaGetSymbolAddress(&p, g_msg_conn); float* msg_conn = (float*)p;
    cudaGetSymbolAddress(&p, g_agg_conn); float* agg_conn = (float*)p;
    cudaGetSymbolAddress(&p, g_agg_ip);   float* agg_ip   = (float*)p;
    cudaGetSymbolAddress(&p, g_zr_ip);    float* zr_ip    = (float*)p;
    cudaGetSymbolAddress(&p, g_zr_c);     float* zr_c     = (float*)p;
    cudaGetSymbolAddress(&p, g_xh_ip);    float* xh_ip    = (float*)p;
    cudaGetSymbolAddress(&p, g_hh_ip);    float* hh_ip    = (float*)p;
    cudaGetSymbolAddress(&p, g_xh_c);     float* xh_c     = (float*)p;
    cudaGetSymbolAddress(&p, g_hh_c);     float* hh_c     = (float*)p;
    cudaGetSymbolAddress(&p, g_rc_conn);  float* rc_conn  = (float*)p;
    cudaGetSymbolAddress(&p, g_rc_ip);    float* rc_ip    = (float*)p;
    cudaGetSymbolAddress(&p, g_H1);       float* H1       = (float*)p;
    cudaGetSymbolAddress(&p, g_H2);       float* H2       = (float*)p;

    __nv_bfloat16 *ipcat_h, *ipcat_l, *conncat_h, *conncat_l;
    __nv_bfloat16 *gik_h, *gik_l, *gir_h, *gir_l, *gck_h, *gck_l, *gcr_h, *gcr_l;
    __nv_bfloat16 *wr1_h, *wr1_l, *wr2_h, *wr2_l;
    cudaGetSymbolAddress(&p, g_ipcat_h);   ipcat_h   = (__nv_bfloat16*)p;
    cudaGetSymbolAddress(&p, g_ipcat_l);   ipcat_l   = (__nv_bfloat16*)p;
    cudaGetSymbolAddress(&p, g_conncat_h); conncat_h = (__nv_bfloat16*)p;
    cudaGetSymbolAddress(&p, g_conncat_l); conncat_l = (__nv_bfloat16*)p;
    cudaGetSymbolAddress(&p, g_gik_h); gik_h = (__nv_bfloat16*)p;
    cudaGetSymbolAddress(&p, g_gik_l); gik_l = (__nv_bfloat16*)p;
    cudaGetSymbolAddress(&p, g_gir_h); gir_h = (__nv_bfloat16*)p;
    cudaGetSymbolAddress(&p, g_gir_l); gir_l = (__nv_bfloat16*)p;
    cudaGetSymbolAddress(&p, g_gck_h); gck_h = (__nv_bfloat16*)p;
    cudaGetSymbolAddress(&p, g_gck_l); gck_l = (__nv_bfloat16*)p;
    cudaGetSymbolAddress(&p, g_gcr_h); gcr_h = (__nv_bfloat16*)p;
    cudaGetSymbolAddress(&p, g_gcr_l); gcr_l = (__nv_bfloat16*)p;
    cudaGetSymbolAddress(&p, g_wr1_h); wr1_h = (__nv_bfloat16*)p;
    cudaGetSymbolAddress(&p, g_wr1_l); wr1_l = (__nv_bfloat16*)p;
    cudaGetSymbolAddress(&p, g_wr2_h); wr2_h = (__nv_bfloat16*)p;
    cudaGetSymbolAddress(&p, g_wr2_l); wr2_l = (__nv_bfloat16*)p;

    // --- merged weight prep (one launch; 286720 elements total) ---
    prep_all<<<(286720 + 255) / 256, 256>>>(W_m1, W_m2, gik, gir, gck, gcr, Wr1, Wr2);

    // --- segment counts + state init ---
    zero_rc<<<(N_CONN + 255) / 256, 256>>>(rc_conn, rc_ip);
    count2<<<(2 * N_E + 255) / 256, 256>>>(d_i2c, d_c2i, rc_conn, rc_ip);
    recip2<<<(N_CONN + 255) / 256, 256>>>(rc_conn, rc_ip);
    init_states<<<(N_CONN * D128 + 255) / 256, 256>>>(ip, conn, feat);

    const int edge_blocks = (N_E * 32 + 255) / 256;
    const int z4c = N_CONN * 32, z4i = N_IP * 32;

    for (int t = 0; t < T_ITERS; t++) {
        // merged message GEMMs: msg_ip = ip @ [W_XA|W_YB]^T, msg_conn = conn @ [W_XB|W_YA]^T
        launch_g128(ip,   ipcat_h,   ipcat_l,   msg_ip,   N_IP,   256, 256, nullptr, nullptr, 0);
        launch_g128(conn, conncat_h, conncat_l, msg_conn, N_CONN, 256, 256, nullptr, nullptr, 0);

        zero2<<<(z4c + z4i + 255) / 256, 256>>>(agg_conn, z4c, agg_ip, z4i);

        // ip->conn: relu(XA[src_ip] + XB[dst_conn] + b_m1) summed per conn
        edge_msg_kernel<<<edge_blocks, 256>>>(s_i2c, d_i2c, msg_ip, msg_conn, 256,
                                              b_m1, agg_conn, N_E);
        // conn->ip: relu(YA[src_conn] + YB[dst_ip] + b_m2) summed per ip
        edge_msg_kernel<<<edge_blocks, 256>>>(s_c2i, d_c2i, msg_conn + 128, msg_ip + 128, 256,
                                              b_m2, agg_ip, N_E);

        // GRU ip: zr (dual-source K=256), xh, hh, gate
        launch_g128(agg_ip, gik_h, gik_l, zr_ip, N_IP, 256, 256, nullptr, rc_ip, 0,
                    ip, gir_h, gir_l);
        launch_g128(agg_ip, gik_h + 256 * 128, gik_l + 256 * 128, xh_ip, N_IP, 128, 128,
                    nullptr, rc_ip, 0);
        launch_g128(ip, gir_h + 256 * 128, gir_l + 256 * 128, hh_ip, N_IP, 128, 128,
                    nullptr, nullptr, 0);
        // GRU conn
        launch_g128(agg_conn, gck_h, gck_l, zr_c, N_CONN, 256, 256, nullptr, rc_conn, 0,
                    conn, gcr_h, gcr_l);
        launch_g128(agg_conn, gck_h + 256 * 128, gck_l + 256 * 128, xh_c, N_CONN, 128, 128,
                    nullptr, rc_conn, 0);
        launch_g128(conn, gcr_h + 256 * 128, gcr_l + 256 * 128, hh_c, N_CONN, 128, 128,
                    nullptr, nullptr, 0);

        gru_gate2<<<(N_IP * 32 + 255) / 256, 256>>>(ip, zr_ip, xh_ip, hh_ip, gib, N_IP);
        gru_gate2<<<(N_CONN * 32 + 255) / 256, 256>>>(conn, zr_c, xh_c, hh_c, gcb, N_CONN);
    }

    // --- readout ---
    launch_g128(conn, wr1_h, wr1_l, H1, N_CONN, 128, 128, br1, nullptr, 1);
    {
        dim3 g((N_CONN + 127) / 128, 1);
        mma_gemm<64><<<g, 256, SMEM64>>>(H1, wr2_h, wr2_l, H2, N_CONN, 64, br2, nullptr, 1,
                                         nullptr, nullptr, nullptr);
    }
    readout_kernel<<<(N_CONN + 127) / 128, 128>>>(H2, Wr3, br3, out, N_CONN);
}